// round 8
// baseline (speedup 1.0000x reference)
#include <cuda_runtime.h>
#include <cstddef>

#define BB 16
#define SS 512
#define DD 384
#define NT 96          // 96 threads = 96 float4 lanes = one 1536B frame

// Sum a per-thread partial across the 96-thread block; all threads get total.
__device__ __forceinline__ int block_sum_96(int s) {
    const int lane = threadIdx.x & 31, warp = threadIdx.x >> 5;
    #pragma unroll
    for (int off = 16; off; off >>= 1) s += __shfl_down_sync(0xffffffffu, s, off);
    __shared__ int ws[3];
    if (lane == 0) ws[warp] = s;
    __syncthreads();
    return ws[0] + ws[1] + ws[2];
}

// One fused launch, three grid segments:
//   [0, 16384)              : scatter — 2 blocks per token, one frame-parity each
//   [16384, +padBlocks)     : zero padding frames [total_b, L)
//   [16384+padBlocks]       : tail (appended out_lengths as float)
// Plain cached stores: output (~94MB) + hidden (12.6MB) fit the 126MB L2, so
// across graph replays the output stays L2-resident (write-in-place, no DRAM).
__global__ void __launch_bounds__(NT) fused_kernel(
    const float* __restrict__ hidden, const int* __restrict__ dur,
    float* __restrict__ out, int L, int padBlocks, int bpb, int tail_n) {
    const int tid = threadIdx.x;
    const int blk = blockIdx.x;
    const int SC = BB * SS * 2;            // 16384 scatter blocks

    if (blk < SC) {
        // ---- scatter: token = blk>>1, this block writes frames of one parity ----
        const int token = blk >> 1;
        const int half  = blk & 1;
        const int b = token >> 9;
        const int t = token & (SS - 1);
        const int* drow = dur + b * SS;
        const int d = drow[t];
        if (d <= half) return;             // parity 1 needs d >= 2

        int s = 0;
        for (int i = tid; i < t; i += NT) s += drow[i];
        const int excl = block_sum_96(s);  // exclusive prefix at t

        const float4 v =
            reinterpret_cast<const float4*>(hidden + (size_t)token * DD)[tid];
        float4* op = reinterpret_cast<float4*>(
            out + ((size_t)b * L + excl) * DD) + tid;
        for (int f = half; f < d; f += 2)
            op[f * (DD / 4)] = v;
        return;
    }

    if (blk < SC + padBlocks) {
        // ---- padding: zero frames [total_b, L) of batch b ----
        const int pb = blk - SC;
        const int b = pb / bpb;
        const int pidx = pb - b * bpb;
        const int* drow = dur + b * SS;

        int s = 0;
        #pragma unroll
        for (int i = tid; i < SS; i += NT) s += drow[i];
        const int total = block_sum_96(s);

        const int warp = tid >> 5, lane = tid & 31;
        const float4 z = make_float4(0.f, 0.f, 0.f, 0.f);
        const int stride = bpb * 3;        // 3 warps per block
        for (int j = pidx * 3 + warp; j < L; j += stride) {
            if (j < total) continue;
            float4* op = reinterpret_cast<float4*>(out + ((size_t)b * L + j) * DD);
            op[lane] = z; op[lane + 32] = z; op[lane + 64] = z;
        }
        return;
    }

    // ---- tail: out_lengths per batch (as float) after the [B,L,D] tensor ----
    {
        float* tail = out + (size_t)BB * L * DD;
        const int warp = tid >> 5, lane = tid & 31;
        for (int b = warp; b < BB; b += 3) {
            const int* drow = dur + b * SS;
            int s = 0;
            #pragma unroll
            for (int i = lane; i < SS; i += 32) s += drow[i];
            #pragma unroll
            for (int off = 16; off; off >>= 1)
                s += __shfl_down_sync(0xffffffffu, s, off);
            if (lane == 0 && b < tail_n) tail[b] = (float)s;
        }
        for (int i = BB + tid; i < tail_n; i += NT) tail[i] = 0.f;
    }
}

extern "C" void kernel_launch(void* const* d_in, const int* in_sizes, int n_in,
                              void* d_out, int out_size) {
    // Identify inputs by element count, not order.
    const float* hidden;
    const int*   dur;
    if (in_sizes[0] == BB * SS) {
        dur    = (const int*)d_in[0];
        hidden = (const float*)d_in[1];
    } else {
        hidden = (const float*)d_in[0];
        dur    = (const int*)d_in[1];
    }
    float* out = (float*)d_out;

    const int frame = BB * DD;                 // 6144 floats per frame-slab
    const int L = out_size / frame;            // frames per batch
    const int tail_n = out_size - L * frame;   // 16 if lengths appended

    const int bpb = (L + 47) / 48;             // pad blocks per batch
    const int padBlocks = bpb * BB;

    const int grid = BB * SS * 2 + padBlocks + 1;
    fused_kernel<<<grid, NT>>>(hidden, dur, out, L, padBlocks, bpb, tail_n);
}

// round 12
// speedup vs baseline: 1.2162x; 1.2162x over previous
#include <cuda_runtime.h>
#include <cstddef>

#define BB 16
#define SS 512
#define DD 384
#define NT 192         // 2 groups x 96 float4 lanes; 6 warps per block

// Sum a per-thread partial across the 192-thread block; all threads get total.
__device__ __forceinline__ int block_sum_192(int s) {
    const int lane = threadIdx.x & 31, warp = threadIdx.x >> 5;
    #pragma unroll
    for (int off = 16; off; off >>= 1) s += __shfl_down_sync(0xffffffffu, s, off);
    __shared__ int ws[6];
    if (lane == 0) ws[warp] = s;
    __syncthreads();
    int tot = 0;
    #pragma unroll
    for (int i = 0; i < 6; i++) tot += ws[i];
    return tot;
}

// One fused launch, three grid segments:
//   [0, 8192)            : scatter — one block per token, ONE scan, two
//                          96-lane groups write interleaved frame parities
//   [8192, +padBlocks)   : zero padding frames [total_b, L)
//   [8192+padBlocks]     : tail (appended out_lengths as float)
__global__ void __launch_bounds__(NT) fused_kernel(
    const float* __restrict__ hidden, const int* __restrict__ dur,
    float* __restrict__ out, int L, int padBlocks, int bpb, int tail_n) {
    const int tid = threadIdx.x;
    const int blk = blockIdx.x;
    const int SC = BB * SS;                // 8192 scatter blocks

    if (blk < SC) {
        // ---- scatter: frames [excl, excl+d) of batch b <- hidden[b,t] ----
        const int token = blk;
        const int b = token >> 9;
        const int t = token & (SS - 1);
        const int* drow = dur + b * SS;
        const int d = drow[t];
        if (d == 0) return;                // uniform branch: whole block exits

        int s = 0;
        for (int i = tid; i < t; i += NT) s += drow[i];
        const int excl = block_sum_192(s); // exclusive prefix at t

        const int g  = tid / 96;           // frame-parity group 0/1
        const int gi = tid - g * 96;       // float4 lane within frame
        if (d <= g) return;                // group 1 idle when d == 1

        const float4 v =
            reinterpret_cast<const float4*>(hidden + (size_t)token * DD)[gi];
        float4* op = reinterpret_cast<float4*>(
            out + ((size_t)b * L + excl) * DD) + gi;
        for (int f = g; f < d; f += 2)     // <= 8 frames per group
            __stcs(op + f * (DD / 4), v);
        return;
    }

    if (blk < SC + padBlocks) {
        // ---- padding: zero frames [total_b, L) of batch b ----
        const int pb = blk - SC;
        const int b = pb / bpb;
        const int pidx = pb - b * bpb;
        const int* drow = dur + b * SS;

        int s = 0;
        #pragma unroll
        for (int i = tid; i < SS; i += NT) s += drow[i];
        const int total = block_sum_192(s);

        const int warp = tid >> 5, lane = tid & 31;
        const float4 z = make_float4(0.f, 0.f, 0.f, 0.f);
        const int stride = bpb * 6;        // 6 warps per block
        for (int j = pidx * 6 + warp; j < L; j += stride) {
            if (j < total) continue;
            float4* op = reinterpret_cast<float4*>(out + ((size_t)b * L + j) * DD);
            __stcs(op + lane, z);
            __stcs(op + lane + 32, z);
            __stcs(op + lane + 64, z);
        }
        return;
    }

    // ---- tail: out_lengths per batch (as float) after the [B,L,D] tensor ----
    {
        float* tail = out + (size_t)BB * L * DD;
        const int warp = tid >> 5, lane = tid & 31;
        for (int b = warp; b < BB; b += 6) {
            const int* drow = dur + b * SS;
            int s = 0;
            #pragma unroll
            for (int i = lane; i < SS; i += 32) s += drow[i];
            #pragma unroll
            for (int off = 16; off; off >>= 1)
                s += __shfl_down_sync(0xffffffffu, s, off);
            if (lane == 0 && b < tail_n) tail[b] = (float)s;
        }
        for (int i = BB + tid; i < tail_n; i += NT) tail[i] = 0.f;
    }
}

extern "C" void kernel_launch(void* const* d_in, const int* in_sizes, int n_in,
                              void* d_out, int out_size) {
    // Identify inputs by element count, not order.
    const float* hidden;
    const int*   dur;
    if (in_sizes[0] == BB * SS) {
        dur    = (const int*)d_in[0];
        hidden = (const float*)d_in[1];
    } else {
        hidden = (const float*)d_in[0];
        dur    = (const int*)d_in[1];
    }
    float* out = (float*)d_out;

    const int frame = BB * DD;                 // 6144 floats per frame-slab
    const int L = out_size / frame;            // frames per batch
    const int tail_n = out_size - L * frame;   // 16 if lengths appended

    const int bpb = (L + 191) / 192;           // pad blocks per batch (~21)
    const int padBlocks = bpb * BB;

    const int grid = BB * SS + padBlocks + 1;
    fused_kernel<<<grid, NT>>>(hidden, dur, out, L, padBlocks, bpb, tail_n);
}

// round 13
// speedup vs baseline: 1.2183x; 1.0017x over previous
#include <cuda_runtime.h>
#include <cstddef>

#define BB 16
#define SS 512
#define DD 384
#define NT 96          // 96 threads = 96 float4 lanes = one 1536B frame

// Sum a per-thread partial across the 96-thread block; all threads get total.
__device__ __forceinline__ int block_sum_96(int s) {
    const int lane = threadIdx.x & 31, warp = threadIdx.x >> 5;
    #pragma unroll
    for (int off = 16; off; off >>= 1) s += __shfl_down_sync(0xffffffffu, s, off);
    __shared__ int ws[3];
    if (lane == 0) ws[warp] = s;
    __syncthreads();
    return ws[0] + ws[1] + ws[2];
}

// One fused launch, three grid segments:
//   [0, 8192)            : scatter — one 96-thread block per token
//   [8192, +padBlocks)   : zero padding frames [total_b, L)
//   [8192+padBlocks]     : tail (appended out_lengths as float)
// All duration scans use int4 loads: 4x fewer LDGs (the LSU-issue floor of
// 1.82 cyc/LDG was costing ~14us of issue pressure with scalar scans).
__global__ void __launch_bounds__(NT) fused_kernel(
    const float* __restrict__ hidden, const int* __restrict__ dur,
    float* __restrict__ out, int L, int padBlocks, int bpb, int tail_n) {
    const int tid = threadIdx.x;
    const int blk = blockIdx.x;
    const int SC = BB * SS;                // 8192 scatter blocks

    if (blk < SC) {
        // ---- scatter: frames [excl, excl+d) of batch b <- hidden[b,t] ----
        const int token = blk;
        const int b = token >> 9;
        const int t = token & (SS - 1);
        const int* drow = dur + b * SS;    // 2048B-aligned (b*2048 bytes)
        const int d = drow[t];
        if (d == 0) return;

        // exclusive prefix sum of drow[0..t) via int4 loads
        const int4* drow4 = reinterpret_cast<const int4*>(drow);
        const int nf = t >> 2;             // full int4 chunks
        int s = 0;
        for (int i = tid; i < nf; i += NT) {
            const int4 v = drow4[i];
            s += v.x + v.y + v.z + v.w;
        }
        if (tid < (t & 3)) s += drow[(nf << 2) + tid];  // <=3 remainder ints
        const int excl = block_sum_96(s);

        const float4 v =
            reinterpret_cast<const float4*>(hidden + (size_t)token * DD)[tid];
        float4* op = reinterpret_cast<float4*>(
            out + ((size_t)b * L + excl) * DD) + tid;
        for (int f = 0; f < d; f++)
            __stcs(op + f * (DD / 4), v);
        return;
    }

    if (blk < SC + padBlocks) {
        // ---- padding: zero frames [total_b, L) of batch b ----
        const int pb = blk - SC;
        const int b = pb / bpb;
        const int pidx = pb - b * bpb;
        const int4* drow4 = reinterpret_cast<const int4*>(dur + b * SS);

        int s = 0;
        #pragma unroll
        for (int i = tid; i < SS / 4; i += NT) {   // 128 int4 chunks
            const int4 v = drow4[i];
            s += v.x + v.y + v.z + v.w;
        }
        const int total = block_sum_96(s);

        const int warp = tid >> 5, lane = tid & 31;
        const float4 z = make_float4(0.f, 0.f, 0.f, 0.f);
        const int stride = bpb * 3;        // 3 warps per block
        for (int j = pidx * 3 + warp; j < L; j += stride) {
            if (j < total) continue;
            float4* op = reinterpret_cast<float4*>(out + ((size_t)b * L + j) * DD);
            __stcs(op + lane, z);
            __stcs(op + lane + 32, z);
            __stcs(op + lane + 64, z);
        }
        return;
    }

    // ---- tail: out_lengths per batch (as float) after the [B,L,D] tensor ----
    {
        float* tail = out + (size_t)BB * L * DD;
        const int warp = tid >> 5, lane = tid & 31;
        for (int b = warp; b < BB; b += 3) {
            const int4* drow4 = reinterpret_cast<const int4*>(dur + b * SS);
            int s = 0;
            #pragma unroll
            for (int i = lane; i < SS / 4; i += 32) {
                const int4 v = drow4[i];
                s += v.x + v.y + v.z + v.w;
            }
            #pragma unroll
            for (int off = 16; off; off >>= 1)
                s += __shfl_down_sync(0xffffffffu, s, off);
            if (lane == 0 && b < tail_n) tail[b] = (float)s;
        }
        for (int i = BB + tid; i < tail_n; i += NT) tail[i] = 0.f;
    }
}

extern "C" void kernel_launch(void* const* d_in, const int* in_sizes, int n_in,
                              void* d_out, int out_size) {
    // Identify inputs by element count, not order.
    const float* hidden;
    const int*   dur;
    if (in_sizes[0] == BB * SS) {
        dur    = (const int*)d_in[0];
        hidden = (const float*)d_in[1];
    } else {
        hidden = (const float*)d_in[0];
        dur    = (const int*)d_in[1];
    }
    float* out = (float*)d_out;

    const int frame = BB * DD;                 // 6144 floats per frame-slab
    const int L = out_size / frame;            // frames per batch
    const int tail_n = out_size - L * frame;   // 16 if lengths appended

    const int bpb = (L + 47) / 48;             // pad blocks per batch
    const int padBlocks = bpb * BB;

    const int grid = BB * SS + padBlocks + 1;
    fused_kernel<<<grid, NT>>>(hidden, dur, out, L, padBlocks, bpb, tail_n);
}